// round 7
// baseline (speedup 1.0000x reference)
#include <cuda_runtime.h>
#include <cstdint>
#include <float.h>

#define D_MODEL   768
#define D_LATENT  12288
#define N_ROWS    16384
#define TOPK      20
#define NCAND     32           // fp32 candidate pool, rescored with replica chain

#define M_TILE    128
#define L_TILE    128
#define K_TILE    32
#define XS_STRIDE 132          // M_TILE + 4 pad
#define WS_STRIDE 132          // L_TILE + 4 pad
#define LB_STRIDE 133          // odd stride -> conflict-free column scan
#define TK_STRIDE 33           // NCAND + 1 pad

#define N_KCHUNK  (D_MODEL / K_TILE)     // 24
#define N_LCHUNK  (D_LATENT / L_TILE)    // 96
#define N_CTAS    (N_ROWS / M_TILE)      // 128

typedef unsigned long long u64;

// 37.75 MB device scratch for W_dec transposed to [D_LATENT][D_MODEL]
__device__ float g_WdecT[(size_t)D_LATENT * D_MODEL];

// ---------------------------------------------------------------------------
// packed f32x2 helpers (full-rate fp32 FMA path)
// ---------------------------------------------------------------------------
__device__ __forceinline__ u64 pack2(float v) {
    u64 r;
    asm("mov.b64 %0, {%1, %1};" : "=l"(r) : "f"(v));
    return r;
}
__device__ __forceinline__ void fma2(u64& d, u64 a, u64 b) {
    asm("fma.rn.f32x2 %0, %1, %2, %0;" : "+l"(d) : "l"(a), "l"(b));
}
__device__ __forceinline__ float2 unpack2(u64 v) {
    float2 r;
    asm("mov.b64 {%0, %1}, %2;" : "=f"(r.x), "=f"(r.y) : "l"(v));
    return r;
}

// ---------------------------------------------------------------------------
// Kernel 1: transpose W_dec [D_MODEL, D_LATENT] -> g_WdecT [D_LATENT, D_MODEL]
// ---------------------------------------------------------------------------
__global__ void transpose_kernel(const float* __restrict__ W) {
    __shared__ float tile[32][33];
    const int l0 = blockIdx.x * 32;
    const int d0 = blockIdx.y * 32;
    const int tx = threadIdx.x, ty = threadIdx.y;
#pragma unroll
    for (int j = 0; j < 32; j += 8)
        tile[ty + j][tx] = W[(size_t)(d0 + ty + j) * D_LATENT + (l0 + tx)];
    __syncthreads();
#pragma unroll
    for (int j = 0; j < 32; j += 8)
        g_WdecT[(size_t)(l0 + ty + j) * D_MODEL + (d0 + tx)] = tile[tx][ty + j];
}

// ---------------------------------------------------------------------------
// Kernel 2: fused encode-GEMM (approx) + streaming top-32 pool +
//           Eigen-GEBP-replica rescore (K panels of kc=248) + top-20 +
//           sparse decode.  Grid: 128 CTAs x 256 threads.
// ---------------------------------------------------------------------------
extern __shared__ float smem[];

__global__ __launch_bounds__(256, 1)
void sae_kernel(const float* __restrict__ x,
                const float* __restrict__ Wenc,
                const float* __restrict__ benc,
                const float* __restrict__ bdec,
                float* __restrict__ out)
{
    float* xs   = smem;                          // [2][K_TILE][XS_STRIDE]
    float* ws   = xs + 2 * K_TILE * XS_STRIDE;   // [2][K_TILE][WS_STRIDE]
    float* latb = ws + 2 * K_TILE * WS_STRIDE;   // [M_TILE][LB_STRIDE]
    float* tv   = latb + M_TILE * LB_STRIDE;     // [M_TILE][TK_STRIDE]
    int*   ti   = (int*)(tv + M_TILE * TK_STRIDE);

    // overlays, live only AFTER the main loop
    float* cdv  = smem;                          // [M_TILE][NCAND] replica vals
    float* sv   = latb;                          // [M_TILE][TOPK] final vals
    int*   si   = (int*)(latb + M_TILE * TOPK);  // [M_TILE][TOPK] final idx

    const int tid = threadIdx.x;
    const int tx  = tid & 15;
    const int ty  = tid >> 4;
    const int row0 = blockIdx.x * M_TILE;

    for (int i = tid; i < M_TILE * TK_STRIDE; i += 256) {
        tv[i] = -FLT_MAX;
        ti[i] = 0;
    }
    __syncthreads();

    float thr = -FLT_MAX;       // scanner state (tid < M_TILE)
    int minpos = 0;

    const int kl = tid & 31;
    const int rl = tid >> 5;
    const float* xbase = x + (size_t)row0 * D_MODEL + kl;

#pragma unroll 1
    for (int lc = 0; lc < N_LCHUNK; ++lc) {
        const int l0 = lc * L_TILE;
        const float* wbase = Wenc + (size_t)l0 * D_MODEL + kl;

        u64 acc[8][4];
#pragma unroll
        for (int i = 0; i < 8; ++i)
#pragma unroll
            for (int j = 0; j < 4; ++j) acc[i][j] = 0ull;

#pragma unroll
        for (int p = 0; p < 16; ++p)
            xs[kl * XS_STRIDE + rl + 8 * p] = xbase[(rl + 8 * p) * D_MODEL];
#pragma unroll
        for (int p = 0; p < 16; ++p)
            ws[kl * WS_STRIDE + rl + 8 * p] = wbase[(rl + 8 * p) * D_MODEL];
        __syncthreads();

#pragma unroll 1
        for (int ki = 0; ki < N_KCHUNK; ++ki) {
            const int cur = ki & 1;
            float xr[16], wr[16];
            if (ki + 1 < N_KCHUNK) {
                const float* xp = xbase + (ki + 1) * K_TILE;
                const float* wp = wbase + (ki + 1) * K_TILE;
#pragma unroll
                for (int p = 0; p < 16; ++p) xr[p] = xp[(rl + 8 * p) * D_MODEL];
#pragma unroll
                for (int p = 0; p < 16; ++p) wr[p] = wp[(rl + 8 * p) * D_MODEL];
            }
            const float* xb = xs + cur * (K_TILE * XS_STRIDE);
            const float* wb = ws + cur * (K_TILE * WS_STRIDE);
#pragma unroll 8
            for (int kk = 0; kk < K_TILE; ++kk) {
                float a[8];
                *(float4*)&a[0] = *(const float4*)(xb + kk * XS_STRIDE + ty * 8);
                *(float4*)&a[4] = *(const float4*)(xb + kk * XS_STRIDE + ty * 8 + 4);
                u64 b[4];
                {
                    ulonglong2 t0 = *(const ulonglong2*)(wb + kk * WS_STRIDE + tx * 8);
                    ulonglong2 t1 = *(const ulonglong2*)(wb + kk * WS_STRIDE + tx * 8 + 4);
                    b[0] = t0.x; b[1] = t0.y; b[2] = t1.x; b[3] = t1.y;
                }
#pragma unroll
                for (int i = 0; i < 8; ++i) {
                    u64 a2 = pack2(a[i]);
                    fma2(acc[i][0], a2, b[0]);
                    fma2(acc[i][1], a2, b[1]);
                    fma2(acc[i][2], a2, b[2]);
                    fma2(acc[i][3], a2, b[3]);
                }
            }
            if (ki + 1 < N_KCHUNK) {
                float* xn = xs + (cur ^ 1) * (K_TILE * XS_STRIDE);
                float* wn = ws + (cur ^ 1) * (K_TILE * WS_STRIDE);
#pragma unroll
                for (int p = 0; p < 16; ++p) xn[kl * XS_STRIDE + rl + 8 * p] = xr[p];
#pragma unroll
                for (int p = 0; p < 16; ++p) wn[kl * WS_STRIDE + rl + 8 * p] = wr[p];
            }
            __syncthreads();
        }

        // epilogue: + b_enc, stash chunk latents
        float bv[8];
#pragma unroll
        for (int j = 0; j < 8; ++j) bv[j] = benc[l0 + tx * 8 + j];
#pragma unroll
        for (int i = 0; i < 8; ++i) {
            float* lr = latb + (ty * 8 + i) * LB_STRIDE + tx * 8;
#pragma unroll
            for (int j = 0; j < 4; ++j) {
                float2 v = unpack2(acc[i][j]);
                lr[2 * j]     = v.x + bv[2 * j];
                lr[2 * j + 1] = v.y + bv[2 * j + 1];
            }
        }
        __syncthreads();

        // streaming top-32 candidate pool: one scanner thread per row
        if (tid < M_TILE) {
            const float* lr = latb + tid * LB_STRIDE;
            float* tvr = tv + tid * TK_STRIDE;
            int*   tir = ti + tid * TK_STRIDE;
#pragma unroll 1
            for (int c = 0; c < L_TILE; ++c) {
                float v = lr[c];
                if (v > thr) {
                    tvr[minpos] = v;
                    tir[minpos] = l0 + c;
                    float m = tvr[0]; int mp = 0;
#pragma unroll
                    for (int j = 1; j < NCAND; ++j) {
                        float t = tvr[j];
                        if (t < m) { m = t; mp = j; }
                    }
                    thr = m; minpos = mp;
                }
            }
        }
        __syncthreads();
    }

    // -----------------------------------------------------------------------
    // Eigen-GEBP replica rescore: per candidate,
    //   s = ((r0 + r1) + r2) + r3,  r_p = sequential fp32 FMA chain over
    //   K panels [0,248) [248,496) [496,744) [744,768)  (kc=248, peel-8 Eigen
    //   heuristic, non-x86 l1=16KB, NEON 3px4 microkernel),
    //   then latent = s + b_enc (separate HLO add).
    // Warp = 32 candidates of one row.
    // -----------------------------------------------------------------------
    {
#pragma unroll 1
        for (int it = 0; it < (M_TILE * NCAND) / 256; ++it) {
            const int chain = it * 256 + tid;
            const int rr = chain >> 5;          // row (constant per warp)
            const int cc = chain & 31;          // candidate
            const int l  = ti[rr * TK_STRIDE + cc];
            const float4* wr4 = (const float4*)(Wenc + (size_t)l * D_MODEL);
            const float4* xr4 = (const float4*)(x + (size_t)(row0 + rr) * D_MODEL);
            float s = 0.f;
            int k4 = 0;
#pragma unroll 1
            for (int p = 0; p < 4; ++p) {
                const int plen4 = (p < 3) ? (248 / 4) : (24 / 4);  // float4 groups
                float r = 0.f;
#pragma unroll 4
                for (int q = 0; q < plen4; ++q) {
                    float4 a = xr4[k4 + q];
                    float4 b = wr4[k4 + q];
                    r = fmaf(a.x, b.x, r);
                    r = fmaf(a.y, b.y, r);
                    r = fmaf(a.z, b.z, r);
                    r = fmaf(a.w, b.w, r);
                }
                s = s + r;                      // panel-join rounding (Eigen C +=)
                k4 += plen4;
            }
            cdv[rr * NCAND + cc] = s + benc[l];
        }
    }
    __syncthreads();

    // top-20 of the 32 replica-scored candidates, jax.lax.top_k tie-breaking
    // (equal values -> lower index wins)
    if (tid < M_TILE) {
        float lval[NCAND];
        int   lidx[NCAND];
#pragma unroll
        for (int j = 0; j < NCAND; ++j) {
            lval[j] = cdv[tid * NCAND + j];
            lidx[j] = ti[tid * TK_STRIDE + j];
        }
        unsigned used = 0;
#pragma unroll 1
        for (int k = 0; k < TOPK; ++k) {
            float best = -FLT_MAX; int bi = 0; int bidx = 0x7FFFFFFF;
#pragma unroll
            for (int j = 0; j < NCAND; ++j) {
                if ((used >> j) & 1u) continue;
                float v = lval[j];
                if (v > best || (v == best && lidx[j] < bidx)) {
                    best = v; bi = j; bidx = lidx[j];
                }
            }
            used |= 1u << bi;
            sv[tid * TOPK + k] = best;
            si[tid * TOPK + k] = bidx;
        }
    }
    __syncthreads();

    // -----------------------------------------------------------------------
    // sparse decode: out[r, :] = b_dec + sum_k val_k * W_decT[idx_k, :]
    // -----------------------------------------------------------------------
    const float bd0 = bdec[tid], bd1 = bdec[tid + 256], bd2 = bdec[tid + 512];
#pragma unroll 1
    for (int r = 0; r < M_TILE; ++r) {
        float a0 = bd0, a1 = bd1, a2 = bd2;
        const float* svr = sv + r * TOPK;
        const int*   sir = si + r * TOPK;
#pragma unroll
        for (int k = 0; k < TOPK; ++k) {
            float v = svr[k];
            const float* w = g_WdecT + (size_t)sir[k] * D_MODEL;
            a0 = fmaf(v, w[tid],       a0);
            a1 = fmaf(v, w[tid + 256], a1);
            a2 = fmaf(v, w[tid + 512], a2);
        }
        float* o = out + (size_t)(row0 + r) * D_MODEL;
        o[tid] = a0; o[tid + 256] = a1; o[tid + 512] = a2;
    }
}

// ---------------------------------------------------------------------------
extern "C" void kernel_launch(void* const* d_in, const int* in_sizes, int n_in,
                              void* d_out, int out_size) {
    const float* x    = (const float*)d_in[0];
    const float* Wenc = (const float*)d_in[1];
    const float* benc = (const float*)d_in[2];
    const float* Wdec = (const float*)d_in[3];
    const float* bdec = (const float*)d_in[4];
    float* out = (float*)d_out;

    constexpr size_t SMEM_BYTES =
        (2 * K_TILE * XS_STRIDE + 2 * K_TILE * WS_STRIDE +
         M_TILE * LB_STRIDE + M_TILE * TK_STRIDE) * sizeof(float) +
        M_TILE * TK_STRIDE * sizeof(int);

    cudaFuncSetAttribute(sae_kernel,
                         cudaFuncAttributeMaxDynamicSharedMemorySize,
                         (int)SMEM_BYTES);

    dim3 tb(32, 8);
    dim3 gb(D_LATENT / 32, D_MODEL / 32);
    transpose_kernel<<<gb, tb>>>(Wdec);
    sae_kernel<<<N_CTAS, 256, SMEM_BYTES>>>(x, Wenc, benc, bdec, out);
}

// round 8
// speedup vs baseline: 1.0010x; 1.0010x over previous
#include <cuda_runtime.h>
#include <cstdint>
#include <float.h>

#define D_MODEL   768
#define D_LATENT  12288
#define N_ROWS    16384
#define TOPK      20
#define NCAND     32           // fp32 candidate pool, rescored with replica chain

#define M_TILE    128
#define L_TILE    128
#define K_TILE    32
#define XS_STRIDE 132          // M_TILE + 4 pad
#define WS_STRIDE 132          // L_TILE + 4 pad
#define LB_STRIDE 133          // odd stride -> conflict-free column scan
#define TK_STRIDE 33           // NCAND + 1 pad

#define N_KCHUNK  (D_MODEL / K_TILE)     // 24
#define N_LCHUNK  (D_LATENT / L_TILE)    // 96
#define N_CTAS    (N_ROWS / M_TILE)      // 128

typedef unsigned long long u64;

// 37.75 MB device scratch for W_dec transposed to [D_LATENT][D_MODEL]
__device__ float g_WdecT[(size_t)D_LATENT * D_MODEL];

// ---------------------------------------------------------------------------
// packed f32x2 helpers (full-rate fp32 FMA path)
// ---------------------------------------------------------------------------
__device__ __forceinline__ u64 pack2(float v) {
    u64 r;
    asm("mov.b64 %0, {%1, %1};" : "=l"(r) : "f"(v));
    return r;
}
__device__ __forceinline__ void fma2(u64& d, u64 a, u64 b) {
    asm("fma.rn.f32x2 %0, %1, %2, %0;" : "+l"(d) : "l"(a), "l"(b));
}
__device__ __forceinline__ float2 unpack2(u64 v) {
    float2 r;
    asm("mov.b64 {%0, %1}, %2;" : "=f"(r.x), "=f"(r.y) : "l"(v));
    return r;
}

// ---------------------------------------------------------------------------
// Kernel 1: transpose W_dec [D_MODEL, D_LATENT] -> g_WdecT [D_LATENT, D_MODEL]
// ---------------------------------------------------------------------------
__global__ void transpose_kernel(const float* __restrict__ W) {
    __shared__ float tile[32][33];
    const int l0 = blockIdx.x * 32;
    const int d0 = blockIdx.y * 32;
    const int tx = threadIdx.x, ty = threadIdx.y;
#pragma unroll
    for (int j = 0; j < 32; j += 8)
        tile[ty + j][tx] = W[(size_t)(d0 + ty + j) * D_LATENT + (l0 + tx)];
    __syncthreads();
#pragma unroll
    for (int j = 0; j < 32; j += 8)
        g_WdecT[(size_t)(l0 + ty + j) * D_MODEL + (d0 + tx)] = tile[tx][ty + j];
}

// ---------------------------------------------------------------------------
// Kernel 2: fused encode-GEMM (approx) + streaming top-32 pool +
//           Eigen-GEBP-replica rescore (K panels of kc=248) + top-20 +
//           sparse decode.  Grid: 128 CTAs x 256 threads.
// ---------------------------------------------------------------------------
extern __shared__ float smem[];

__global__ __launch_bounds__(256, 1)
void sae_kernel(const float* __restrict__ x,
                const float* __restrict__ Wenc,
                const float* __restrict__ benc,
                const float* __restrict__ bdec,
                float* __restrict__ out)
{
    float* xs   = smem;                          // [2][K_TILE][XS_STRIDE]
    float* ws   = xs + 2 * K_TILE * XS_STRIDE;   // [2][K_TILE][WS_STRIDE]
    float* latb = ws + 2 * K_TILE * WS_STRIDE;   // [M_TILE][LB_STRIDE]
    float* tv   = latb + M_TILE * LB_STRIDE;     // [M_TILE][TK_STRIDE]
    int*   ti   = (int*)(tv + M_TILE * TK_STRIDE);

    // overlays, live only AFTER the main loop
    float* cdv  = smem;                          // [M_TILE][NCAND] replica vals
    float* sv   = latb;                          // [M_TILE][TOPK] final vals
    int*   si   = (int*)(latb + M_TILE * TOPK);  // [M_TILE][TOPK] final idx

    const int tid = threadIdx.x;
    const int tx  = tid & 15;
    const int ty  = tid >> 4;
    const int row0 = blockIdx.x * M_TILE;

    for (int i = tid; i < M_TILE * TK_STRIDE; i += 256) {
        tv[i] = -FLT_MAX;
        ti[i] = 0;
    }
    __syncthreads();

    float thr = -FLT_MAX;       // scanner state (tid < M_TILE)
    int minpos = 0;

    const int kl = tid & 31;
    const int rl = tid >> 5;
    const float* xbase = x + (size_t)row0 * D_MODEL + kl;

#pragma unroll 1
    for (int lc = 0; lc < N_LCHUNK; ++lc) {
        const int l0 = lc * L_TILE;
        const float* wbase = Wenc + (size_t)l0 * D_MODEL + kl;

        u64 acc[8][4];
#pragma unroll
        for (int i = 0; i < 8; ++i)
#pragma unroll
            for (int j = 0; j < 4; ++j) acc[i][j] = 0ull;

#pragma unroll
        for (int p = 0; p < 16; ++p)
            xs[kl * XS_STRIDE + rl + 8 * p] = xbase[(rl + 8 * p) * D_MODEL];
#pragma unroll
        for (int p = 0; p < 16; ++p)
            ws[kl * WS_STRIDE + rl + 8 * p] = wbase[(rl + 8 * p) * D_MODEL];
        __syncthreads();

#pragma unroll 1
        for (int ki = 0; ki < N_KCHUNK; ++ki) {
            const int cur = ki & 1;
            float xr[16], wr[16];
            if (ki + 1 < N_KCHUNK) {
                const float* xp = xbase + (ki + 1) * K_TILE;
                const float* wp = wbase + (ki + 1) * K_TILE;
#pragma unroll
                for (int p = 0; p < 16; ++p) xr[p] = xp[(rl + 8 * p) * D_MODEL];
#pragma unroll
                for (int p = 0; p < 16; ++p) wr[p] = wp[(rl + 8 * p) * D_MODEL];
            }
            const float* xb = xs + cur * (K_TILE * XS_STRIDE);
            const float* wb = ws + cur * (K_TILE * WS_STRIDE);
#pragma unroll 8
            for (int kk = 0; kk < K_TILE; ++kk) {
                float a[8];
                *(float4*)&a[0] = *(const float4*)(xb + kk * XS_STRIDE + ty * 8);
                *(float4*)&a[4] = *(const float4*)(xb + kk * XS_STRIDE + ty * 8 + 4);
                u64 b[4];
                {
                    ulonglong2 t0 = *(const ulonglong2*)(wb + kk * WS_STRIDE + tx * 8);
                    ulonglong2 t1 = *(const ulonglong2*)(wb + kk * WS_STRIDE + tx * 8 + 4);
                    b[0] = t0.x; b[1] = t0.y; b[2] = t1.x; b[3] = t1.y;
                }
#pragma unroll
                for (int i = 0; i < 8; ++i) {
                    u64 a2 = pack2(a[i]);
                    fma2(acc[i][0], a2, b[0]);
                    fma2(acc[i][1], a2, b[1]);
                    fma2(acc[i][2], a2, b[2]);
                    fma2(acc[i][3], a2, b[3]);
                }
            }
            if (ki + 1 < N_KCHUNK) {
                float* xn = xs + (cur ^ 1) * (K_TILE * XS_STRIDE);
                float* wn = ws + (cur ^ 1) * (K_TILE * WS_STRIDE);
#pragma unroll
                for (int p = 0; p < 16; ++p) xn[kl * XS_STRIDE + rl + 8 * p] = xr[p];
#pragma unroll
                for (int p = 0; p < 16; ++p) wn[kl * WS_STRIDE + rl + 8 * p] = wr[p];
            }
            __syncthreads();
        }

        // epilogue: + b_enc, stash chunk latents
        float bv[8];
#pragma unroll
        for (int j = 0; j < 8; ++j) bv[j] = benc[l0 + tx * 8 + j];
#pragma unroll
        for (int i = 0; i < 8; ++i) {
            float* lr = latb + (ty * 8 + i) * LB_STRIDE + tx * 8;
#pragma unroll
            for (int j = 0; j < 4; ++j) {
                float2 v = unpack2(acc[i][j]);
                lr[2 * j]     = v.x + bv[2 * j];
                lr[2 * j + 1] = v.y + bv[2 * j + 1];
            }
        }
        __syncthreads();

        // streaming top-32 candidate pool: one scanner thread per row
        if (tid < M_TILE) {
            const float* lr = latb + tid * LB_STRIDE;
            float* tvr = tv + tid * TK_STRIDE;
            int*   tir = ti + tid * TK_STRIDE;
#pragma unroll 1
            for (int c = 0; c < L_TILE; ++c) {
                float v = lr[c];
                if (v > thr) {
                    tvr[minpos] = v;
                    tir[minpos] = l0 + c;
                    float m = tvr[0]; int mp = 0;
#pragma unroll
                    for (int j = 1; j < NCAND; ++j) {
                        float t = tvr[j];
                        if (t < m) { m = t; mp = j; }
                    }
                    thr = m; minpos = mp;
                }
            }
        }
        __syncthreads();
    }

    // -----------------------------------------------------------------------
    // Eigen-GEBP replica rescore: per candidate,
    //   s = ((r0 + r1) + r2) + r3,  r_p = sequential fp32 FMA chain over
    //   K panels [0,248) [248,496) [496,744) [744,768)  (kc=248, peel-8 Eigen
    //   heuristic, non-x86 l1=16KB, NEON 3px4 microkernel),
    //   then latent = s + b_enc (separate HLO add).
    // Warp = 32 candidates of one row.
    // -----------------------------------------------------------------------
    {
#pragma unroll 1
        for (int it = 0; it < (M_TILE * NCAND) / 256; ++it) {
            const int chain = it * 256 + tid;
            const int rr = chain >> 5;          // row (constant per warp)
            const int cc = chain & 31;          // candidate
            const int l  = ti[rr * TK_STRIDE + cc];
            const float4* wr4 = (const float4*)(Wenc + (size_t)l * D_MODEL);
            const float4* xr4 = (const float4*)(x + (size_t)(row0 + rr) * D_MODEL);
            float s = 0.f;
            int k4 = 0;
#pragma unroll 1
            for (int p = 0; p < 4; ++p) {
                const int plen4 = (p < 3) ? (248 / 4) : (24 / 4);  // float4 groups
                float r = 0.f;
#pragma unroll 4
                for (int q = 0; q < plen4; ++q) {
                    float4 a = xr4[k4 + q];
                    float4 b = wr4[k4 + q];
                    r = fmaf(a.x, b.x, r);
                    r = fmaf(a.y, b.y, r);
                    r = fmaf(a.z, b.z, r);
                    r = fmaf(a.w, b.w, r);
                }
                s = s + r;                      // panel-join rounding (Eigen C +=)
                k4 += plen4;
            }
            cdv[rr * NCAND + cc] = s + benc[l];
        }
    }
    __syncthreads();

    // top-20 of the 32 replica-scored candidates, jax.lax.top_k tie-breaking
    // (equal values -> lower index wins)
    if (tid < M_TILE) {
        float lval[NCAND];
        int   lidx[NCAND];
#pragma unroll
        for (int j = 0; j < NCAND; ++j) {
            lval[j] = cdv[tid * NCAND + j];
            lidx[j] = ti[tid * TK_STRIDE + j];
        }
        unsigned used = 0;
#pragma unroll 1
        for (int k = 0; k < TOPK; ++k) {
            float best = -FLT_MAX; int bi = 0; int bidx = 0x7FFFFFFF;
#pragma unroll
            for (int j = 0; j < NCAND; ++j) {
                if ((used >> j) & 1u) continue;
                float v = lval[j];
                if (v > best || (v == best && lidx[j] < bidx)) {
                    best = v; bi = j; bidx = lidx[j];
                }
            }
            used |= 1u << bi;
            sv[tid * TOPK + k] = best;
            si[tid * TOPK + k] = bidx;
        }
    }
    __syncthreads();

    // -----------------------------------------------------------------------
    // sparse decode: out[r, :] = b_dec + sum_k val_k * W_decT[idx_k, :]
    // -----------------------------------------------------------------------
    const float bd0 = bdec[tid], bd1 = bdec[tid + 256], bd2 = bdec[tid + 512];
#pragma unroll 1
    for (int r = 0; r < M_TILE; ++r) {
        float a0 = bd0, a1 = bd1, a2 = bd2;
        const float* svr = sv + r * TOPK;
        const int*   sir = si + r * TOPK;
#pragma unroll
        for (int k = 0; k < TOPK; ++k) {
            float v = svr[k];
            const float* w = g_WdecT + (size_t)sir[k] * D_MODEL;
            a0 = fmaf(v, w[tid],       a0);
            a1 = fmaf(v, w[tid + 256], a1);
            a2 = fmaf(v, w[tid + 512], a2);
        }
        float* o = out + (size_t)(row0 + r) * D_MODEL;
        o[tid] = a0; o[tid + 256] = a1; o[tid + 512] = a2;
    }
}

// ---------------------------------------------------------------------------
extern "C" void kernel_launch(void* const* d_in, const int* in_sizes, int n_in,
                              void* d_out, int out_size) {
    const float* x    = (const float*)d_in[0];
    const float* Wenc = (const float*)d_in[1];
    const float* benc = (const float*)d_in[2];
    const float* Wdec = (const float*)d_in[3];
    const float* bdec = (const float*)d_in[4];
    float* out = (float*)d_out;

    constexpr size_t SMEM_BYTES =
        (2 * K_TILE * XS_STRIDE + 2 * K_TILE * WS_STRIDE +
         M_TILE * LB_STRIDE + M_TILE * TK_STRIDE) * sizeof(float) +
        M_TILE * TK_STRIDE * sizeof(int);

    cudaFuncSetAttribute(sae_kernel,
                         cudaFuncAttributeMaxDynamicSharedMemorySize,
                         (int)SMEM_BYTES);

    dim3 tb(32, 8);
    dim3 gb(D_LATENT / 32, D_MODEL / 32);
    transpose_kernel<<<gb, tb>>>(Wdec);
    sae_kernel<<<N_CTAS, 256, SMEM_BYTES>>>(x, Wenc, benc, bdec, out);
}